// round 11
// baseline (speedup 1.0000x reference)
#include <cuda_runtime.h>
#include <cstddef>

#define NN 50000
#define NE 800000
#define DD 128
#define NSTEPS 5
#define EPSF 1e-5f

typedef unsigned long long ull;

// ---------------- scratch (static __device__ — no allocation) ----------------
static __device__ float g_hn  [NN*DD];
static __device__ float g_h   [NN*DD];
static __device__ float g_x   [NN*DD];
static __device__ float g_eacc[NN*DD];
static __device__ int   g_cnt [NN];
static __device__ int   g_deg [NN];
static __device__ float g_dis [NN];
static __device__ float g_selfw[NN];
static __device__ int   g_off [NN+1];
static __device__ int   g_cur [NN];
static __device__ int   g_csrc[NE];
static __device__ float g_ccoef[NE];
static __device__ float g_bnsum[DD];
static __device__ float g_bnsq [DD];

// ---------------- helpers ----------------
__device__ __forceinline__ void red_add_v4(float* p, float a, float b, float c, float d){
    asm volatile("red.global.add.v4.f32 [%0], {%1,%2,%3,%4};"
                 :: "l"(p), "f"(a), "f"(b), "f"(c), "f"(d) : "memory");
}
__device__ __forceinline__ ull fma2(ull a, ull b, ull c){
    ull d;
    asm("fma.rn.f32x2 %0, %1, %2, %3;" : "=l"(d) : "l"(a), "l"(b), "l"(c));
    return d;
}
__device__ __forceinline__ float pairsum(ull p){
    unsigned lo, hi;
    asm("mov.b64 {%0,%1}, %2;" : "=r"(lo), "=r"(hi) : "l"(p));
    return __uint_as_float(lo) + __uint_as_float(hi);
}
__device__ __forceinline__ ull pack2(float x, float y){
    ull p;
    asm("mov.b64 %0, {%1,%2};" : "=l"(p) : "r"(__float_as_uint(x)), "r"(__float_as_uint(y)));
    return p;
}

// Load weights [KD][128] row-major -> k-pair interleaved smem:
// sW2[(kp*128 + c)*2 + {0,1}] = W[2kp][c], W[2kp+1][c]   (odd KD: pad 0)
template<int KD, int NTHR>
__device__ __forceinline__ void load_w2(const float* __restrict__ W, float* __restrict__ sW2, int t){
    constexpr int KP = (KD + 1) / 2;
    for (int i = t; i < KP*128; i += NTHR){
        int kp = i >> 7, c = i & 127;
        float w0 = W[(2*kp)*128 + c];
        float w1 = (2*kp+1 < KD) ? W[(2*kp+1)*128 + c] : 0.f;
        reinterpret_cast<float2*>(sW2)[i] = make_float2(w0, w1);
    }
}

// r7 proven LDS core (used only for tiny-K layer-1 of node/edge encoders).
template<int KPAIRS>
__device__ __forceinline__ void gemm_core2(const float* __restrict__ xrow, int stride,
                                           const float* __restrict__ sW2, int lane,
                                           ull acc2[8][4])
{
#pragma unroll
    for (int r=0;r<8;r++){ acc2[r][0]=0ull; acc2[r][1]=0ull; acc2[r][2]=0ull; acc2[r][3]=0ull; }
#pragma unroll 2
    for (int kp=0; kp<KPAIRS; kp++){
        const ulonglong2* wp = reinterpret_cast<const ulonglong2*>(sW2 + kp*256);
        ulonglong2 wA = wp[lane*2+0];
        ulonglong2 wB = wp[lane*2+1];
        ull a[8];
#pragma unroll
        for (int r=0;r<8;r++)
            a[r] = *reinterpret_cast<const ull*>(xrow + r*stride + kp*2);
#pragma unroll
        for (int r=0;r<8;r++){
            acc2[r][0] = fma2(a[r], wA.x, acc2[r][0]);
            acc2[r][1] = fma2(a[r], wA.y, acc2[r][1]);
            acc2[r][2] = fma2(a[r], wB.x, acc2[r][2]);
            acc2[r][3] = fma2(a[r], wB.y, acc2[r][3]);
        }
    }
}

// Shuffle core: activations register-resident per warp (lane c owns cols 4c..4c+3
// of the warp's 8 rows as vlo=(x,y), vhi=(z,w)). k-pair kp lives in lane kp>>1,
// half kp&1. Weights from smem (k-pair interleaved). No smem for activations.
__device__ __forceinline__ void gemm_shfl(const ull vlo[8], const ull vhi[8],
                                          const float* __restrict__ sW2, int lane,
                                          ull acc2[8][4])
{
#pragma unroll
    for (int r=0;r<8;r++){ acc2[r][0]=0ull; acc2[r][1]=0ull; acc2[r][2]=0ull; acc2[r][3]=0ull; }
#pragma unroll 2
    for (int kp=0; kp<64; kp++){
        const ulonglong2* wp = reinterpret_cast<const ulonglong2*>(sW2 + kp*256);
        ulonglong2 wA = wp[lane*2+0];
        ulonglong2 wB = wp[lane*2+1];
        const int srcl = kp >> 1;
        ull a[8];
        if (kp & 1){
#pragma unroll
            for (int r=0;r<8;r++) a[r] = __shfl_sync(0xffffffffu, vhi[r], srcl);
        } else {
#pragma unroll
            for (int r=0;r<8;r++) a[r] = __shfl_sync(0xffffffffu, vlo[r], srcl);
        }
#pragma unroll
        for (int r=0;r<8;r++){
            acc2[r][0] = fma2(a[r], wA.x, acc2[r][0]);
            acc2[r][1] = fma2(a[r], wA.y, acc2[r][1]);
            acc2[r][2] = fma2(a[r], wB.x, acc2[r][2]);
            acc2[r][3] = fma2(a[r], wB.y, acc2[r][3]);
        }
    }
}

// ---------------- fused 3-layer MLP (+LayerNorm): 128-row tile, 512 thr, 0 post-stage barriers ----
// MODE 0: node encoder -> store rows; MODE 1: edge encoder -> LN + red-scatter to out[src];
// MODE 2: decoder -> [nrows,128] input (direct LDG), store rows.
template<int INDIM, int MODE>
__global__ void __launch_bounds__(512,1)
mlp3_kernel(const float* __restrict__ in,
            const float* __restrict__ W1, const float* __restrict__ b1,
            const float* __restrict__ W2, const float* __restrict__ b2,
            const float* __restrict__ W3, const float* __restrict__ b3,
            const float* __restrict__ lng, const float* __restrict__ lnb,
            const int* __restrict__ srcIdx,
            float* __restrict__ out, int nrows)
{
    extern __shared__ float sm[];
    float* sW1  = sm;                  // 16384 (only (INDIM+1)/2*256 used)
    float* sW2  = sm + 16384;          // 16384
    float* sW3  = sm + 32768;          // 16384
    float* sIn  = sm + 49152;          // 128*20 = 2560 (MODE 0/1 only)
    float* sG   = sIn + 2560;          // 128
    float* sBt  = sG + 128;            // 128
    float* sB1  = sBt + 128;           // 128
    float* sB2  = sB1 + 128;           // 128
    float* sB3  = sB2 + 128;           // 128
    int*   sSrc = (int*)(sB3 + 128);   // 128 ints

    const int t    = threadIdx.x;
    const int lane = t & 31;
    const int warp = t >> 5;           // 0..15
    const int row0 = blockIdx.x * 128;
    constexpr int INPAD = (INDIM==19) ? 20 : 4;

    if (t < 128){ sG[t]=lng[t]; sBt[t]=lnb[t]; sB1[t]=b1[t]; sB2[t]=b2[t]; sB3[t]=b3[t]; }

    if constexpr (MODE != 2){
        for (int i=t;i<128*INPAD;i+=512){
            int r=i/INPAD, k=i-r*INPAD;
            sIn[i] = (k < INDIM && row0+r < nrows) ? in[(size_t)(row0+r)*INDIM+k] : 0.f;
        }
        load_w2<INDIM,512>(W1, sW1, t);
    } else {
        load_w2<128,512>(W1, sW1, t);
    }
    if constexpr (MODE == 1){ if (t<128) sSrc[t]=srcIdx[row0+t]; }
    load_w2<128,512>(W2, sW2, t);
    load_w2<128,512>(W3, sW3, t);
    __syncthreads();   // the ONLY barrier

    ull acc2[8][4];
    ull vlo[8], vhi[8];

    // ---- layer 1 ----
    if constexpr (MODE == 2){
#pragma unroll
        for (int r=0;r<8;r++){
            int row = row0 + warp*8 + r;
            float4 f = (row < nrows) ? reinterpret_cast<const float4*>(in + (size_t)row*128)[lane]
                                     : make_float4(0.f,0.f,0.f,0.f);
            vlo[r] = pack2(f.x, f.y); vhi[r] = pack2(f.z, f.w);
        }
        gemm_shfl(vlo, vhi, sW1, lane, acc2);
    } else {
        gemm_core2<(INDIM+1)/2>(sIn + warp*8*INPAD, INPAD, sW1, lane, acc2);
    }
    {
        float4 b4 = reinterpret_cast<const float4*>(sB1)[lane];
#pragma unroll
        for (int r=0;r<8;r++){
            float x = pairsum(acc2[r][0])+b4.x; x=(x>0.f)?x:0.05f*x;
            float y = pairsum(acc2[r][1])+b4.y; y=(y>0.f)?y:0.05f*y;
            float z = pairsum(acc2[r][2])+b4.z; z=(z>0.f)?z:0.05f*z;
            float w = pairsum(acc2[r][3])+b4.w; w=(w>0.f)?w:0.05f*w;
            vlo[r]=pack2(x,y); vhi[r]=pack2(z,w);
        }
    }
    // ---- layer 2 ----
    gemm_shfl(vlo, vhi, sW2, lane, acc2);
    {
        float4 b4 = reinterpret_cast<const float4*>(sB2)[lane];
#pragma unroll
        for (int r=0;r<8;r++){
            float x = pairsum(acc2[r][0])+b4.x; x=(x>0.f)?x:0.05f*x;
            float y = pairsum(acc2[r][1])+b4.y; y=(y>0.f)?y:0.05f*y;
            float z = pairsum(acc2[r][2])+b4.z; z=(z>0.f)?z:0.05f*z;
            float w = pairsum(acc2[r][3])+b4.w; w=(w>0.f)?w:0.05f*w;
            vlo[r]=pack2(x,y); vhi[r]=pack2(z,w);
        }
    }
    // ---- layer 3 + LayerNorm ----
    gemm_shfl(vlo, vhi, sW3, lane, acc2);
    {
        float4 b4 = reinterpret_cast<const float4*>(sB3)[lane];
        float4 gv = reinterpret_cast<const float4*>(sG)[lane];
        float4 bv = reinterpret_cast<const float4*>(sBt)[lane];
#pragma unroll
        for (int r=0;r<8;r++){
            float x = pairsum(acc2[r][0])+b4.x;
            float y = pairsum(acc2[r][1])+b4.y;
            float z = pairsum(acc2[r][2])+b4.z;
            float w = pairsum(acc2[r][3])+b4.w;
            float s = x+y+z+w;
            float q = x*x+y*y+z*z+w*w;
#pragma unroll
            for (int o=16;o>0;o>>=1){
                s += __shfl_xor_sync(0xffffffffu, s, o);
                q += __shfl_xor_sync(0xffffffffu, q, o);
            }
            float m   = s * (1.f/128.f);
            float var = q * (1.f/128.f) - m*m;
            float rs  = rsqrtf(var + EPSF);
            float4 o4;
            o4.x = (x-m)*rs*gv.x + bv.x;
            o4.y = (y-m)*rs*gv.y + bv.y;
            o4.z = (z-m)*rs*gv.z + bv.z;
            o4.w = (w-m)*rs*gv.w + bv.w;
            int row = warp*8 + r;
            if constexpr (MODE == 1){
                int sidx = sSrc[row];
                red_add_v4(out + (size_t)sidx*128 + lane*4, o4.x, o4.y, o4.z, o4.w);
            } else {
                if (row0 + row < nrows)
                    reinterpret_cast<float4*>(out + (size_t)(row0+row)*128)[lane] = o4;
            }
        }
    }
}

// ---------------- conv GEMM: shfl core, direct-LDG input, fused BN, 64-row tile, 2 CTA/SM ----
__global__ void __launch_bounds__(256,2)
gemm_kernel(const float* __restrict__ in, const float* __restrict__ W,
            float* __restrict__ out, int nrows,
            const float* __restrict__ bnsum, const float* __restrict__ bnsq,
            const float* __restrict__ bng, const float* __restrict__ bnb, int useBN,
            float* __restrict__ zsum, float* __restrict__ zsq)
{
    extern __shared__ float sm[];
    float* sW2    = sm;               // 16384
    float* sScale = sm + 16384;       // 128
    float* sShift = sScale + 128;     // 128

    const int t    = threadIdx.x;
    const int lane = t & 31;
    const int warp = t >> 5;
    const int row0 = blockIdx.x * 64;

    // zero BN accumulators for the upcoming agg pass (conv1 only, one block)
    if (zsum && blockIdx.x == 0 && t < 128){ zsum[t] = 0.f; zsq[t] = 0.f; }

    if (t < 128){
        if (useBN){
            float mm = bnsum[t]*(1.f/NN);
            float vv = bnsq[t]*(1.f/NN) - mm*mm;
            float rr = rsqrtf(vv + EPSF);
            sScale[t] = rr*bng[t];
            sShift[t] = bnb[t] - mm*rr*bng[t];
        } else { sScale[t]=1.f; sShift[t]=0.f; }
    }
    load_w2<128,256>(W, sW2, t);
    __syncthreads();

    ull vlo[8], vhi[8];
    {
        float4 sc = reinterpret_cast<const float4*>(sScale)[lane];
        float4 sh = reinterpret_cast<const float4*>(sShift)[lane];
#pragma unroll
        for (int r=0;r<8;r++){
            int row = row0 + warp*8 + r;
            float4 f = (row < nrows) ? reinterpret_cast<const float4*>(in + (size_t)row*128)[lane]
                                     : make_float4(0.f,0.f,0.f,0.f);
            f.x = f.x*sc.x + sh.x; f.y = f.y*sc.y + sh.y;
            f.z = f.z*sc.z + sh.z; f.w = f.w*sc.w + sh.w;
            vlo[r] = pack2(f.x,f.y); vhi[r] = pack2(f.z,f.w);
        }
    }
    ull acc2[8][4];
    gemm_shfl(vlo, vhi, sW2, lane, acc2);
#pragma unroll
    for (int r=0;r<8;r++){
        int row = row0 + warp*8 + r;
        if (row < nrows)
            reinterpret_cast<float4*>(out + (size_t)row*128)[lane] =
                make_float4(pairsum(acc2[r][0]),pairsum(acc2[r][1]),
                            pairsum(acc2[r][2]),pairsum(acc2[r][3]));
    }
}

// ---------------- fused CSR aggregation + epilogue (warp per node) ----------------
template<int MODE>
__global__ void __launch_bounds__(256)
agg_kernel(const float* __restrict__ h, const int* __restrict__ off,
           const int* __restrict__ csrc, const float* __restrict__ ccoef,
           const float* __restrict__ selfw, const float* __restrict__ bias,
           float* __restrict__ xout, float* __restrict__ hn,
           float* __restrict__ bnsum, float* __restrict__ bnsq)
{
    __shared__ float sbs[DD], sbq[DD];
    const int t = threadIdx.x, lane = t & 31, w = t >> 5;
    if constexpr (MODE == 1){
        if (t < 128){ sbs[t]=0.f; sbq[t]=0.f; }
        __syncthreads();
    }
    float4 b4 = reinterpret_cast<const float4*>(bias)[lane];
    float s0=0.f,s1=0.f,s2=0.f,s3=0.f,q0=0.f,q1=0.f,q2=0.f,q3=0.f;
    const int nwarps = gridDim.x * 8;

    for (int n = blockIdx.x*8 + w; n < NN; n += nwarps){
        int e0 = off[n], e1 = off[n+1];
        float ax=0.f, ay=0.f, az=0.f, aw=0.f;
        int i = e0;
        for (; i+1 < e1; i += 2){
            int   sA = csrc[i];   float cA = ccoef[i];
            int   sB = csrc[i+1]; float cB = ccoef[i+1];
            float4 vA = reinterpret_cast<const float4*>(h + (size_t)sA*DD)[lane];
            float4 vB = reinterpret_cast<const float4*>(h + (size_t)sB*DD)[lane];
            ax += vA.x*cA + vB.x*cB; ay += vA.y*cA + vB.y*cB;
            az += vA.z*cA + vB.z*cB; aw += vA.w*cA + vB.w*cB;
        }
        if (i < e1){
            int sA = csrc[i]; float cA = ccoef[i];
            float4 vA = reinterpret_cast<const float4*>(h + (size_t)sA*DD)[lane];
            ax += vA.x*cA; ay += vA.y*cA; az += vA.z*cA; aw += vA.w*cA;
        }
        float4 hv = reinterpret_cast<const float4*>(h + (size_t)n*DD)[lane];
        float sw = selfw[n];
        ax += hv.x*sw + b4.x; ay += hv.y*sw + b4.y;
        az += hv.z*sw + b4.z; aw += hv.w*sw + b4.w;
        if constexpr (MODE == 1){
            ax = (ax>0.f)?ax:0.05f*ax; ay = (ay>0.f)?ay:0.05f*ay;
            az = (az>0.f)?az:0.05f*az; aw = (aw>0.f)?aw:0.05f*aw;
            reinterpret_cast<float4*>(xout + (size_t)n*DD)[lane] = make_float4(ax,ay,az,aw);
            s0+=ax;s1+=ay;s2+=az;s3+=aw;
            q0+=ax*ax;q1+=ay*ay;q2+=az*az;q3+=aw*aw;
        } else {
            float4 o = reinterpret_cast<float4*>(hn + (size_t)n*DD)[lane];
            o.x+=ax; o.y+=ay; o.z+=az; o.w+=aw;
            reinterpret_cast<float4*>(hn + (size_t)n*DD)[lane] = o;
        }
    }
    if constexpr (MODE == 1){
        atomicAdd(&sbs[lane*4+0],s0); atomicAdd(&sbs[lane*4+1],s1);
        atomicAdd(&sbs[lane*4+2],s2); atomicAdd(&sbs[lane*4+3],s3);
        atomicAdd(&sbq[lane*4+0],q0); atomicAdd(&sbq[lane*4+1],q1);
        atomicAdd(&sbq[lane*4+2],q2); atomicAdd(&sbq[lane*4+3],q3);
        __syncthreads();
        if (t < 128){ atomicAdd(&bnsum[t], sbs[t]); atomicAdd(&bnsq[t], sbq[t]); }
    }
}

// ---------------- prep kernels ----------------
__global__ void deg_kernel(const int* __restrict__ src, const int* __restrict__ dst,
                           int* __restrict__ degD, int* __restrict__ cntS){
    int e = blockIdx.x*256 + threadIdx.x;
    if (e < NE){ atomicAdd(&degD[dst[e]], 1); atomicAdd(&cntS[src[e]], 1); }
}
__global__ void nodeprep_kernel(const int* __restrict__ degD,
                                float* __restrict__ dis, float* __restrict__ selfw){
    int n = blockIdx.x*256 + threadIdx.x;
    if (n < NN){
        float d = (float)degD[n] + 1.0f;
        dis[n] = rsqrtf(d);
        selfw[n] = 1.0f/d;
    }
}
__global__ void scan_kernel(const int* __restrict__ degD, int* __restrict__ off){
    __shared__ int sh[32];
    __shared__ int carry;
    const int t = threadIdx.x, lane = t & 31, w = t >> 5;
    if (t == 0){ carry = 0; off[0] = 0; }
    __syncthreads();
    for (int base = 0; base < NN; base += 1024){
        int i = base + t;
        int v = (i < NN) ? degD[i] : 0;
        int x = v;
#pragma unroll
        for (int o=1;o<32;o<<=1){ int y=__shfl_up_sync(0xffffffffu,x,o); if (lane>=o) x+=y; }
        if (lane == 31) sh[w] = x;
        __syncthreads();
        if (w == 0){
            int y = sh[lane];
#pragma unroll
            for (int o=1;o<32;o<<=1){ int z=__shfl_up_sync(0xffffffffu,y,o); if (lane>=o) y+=z; }
            sh[lane] = y;
        }
        __syncthreads();
        int add = (w > 0) ? sh[w-1] : 0;
        int incl = x + add + carry;
        if (i < NN) off[i+1] = incl;
        __syncthreads();
        if (t == 1023) carry = incl;
        __syncthreads();
    }
}
__global__ void fill_kernel(const int* __restrict__ src, const int* __restrict__ dst,
                            const float* __restrict__ dis, const int* __restrict__ off,
                            int* __restrict__ cur, int* __restrict__ csrc, float* __restrict__ ccoef){
    int e = blockIdx.x*256 + threadIdx.x;
    if (e < NE){
        int d = dst[e], s = src[e];
        int pos = off[d] + atomicAdd(&cur[d], 1);
        csrc[pos]  = s;
        ccoef[pos] = dis[s]*dis[d];
    }
}
__global__ void encfin_kernel(float* __restrict__ hn, const float* __restrict__ eacc,
                              const int* __restrict__ cnt){
    int i4 = blockIdx.x*256 + threadIdx.x;
    if (i4 >= NN*32) return;
    int n = i4 >> 5;
    float inv = 1.0f / fmaxf((float)cnt[n], 1.0f);
    float4 a  = reinterpret_cast<const float4*>(eacc)[i4];
    float4 hh = reinterpret_cast<float4*>(hn)[i4];
    hh.x += a.x*inv; hh.y += a.y*inv; hh.z += a.z*inv; hh.w += a.w*inv;
    reinterpret_cast<float4*>(hn)[i4] = hh;
}

// ---------------- launcher ----------------
extern "C" void kernel_launch(void* const* d_in, const int* in_sizes, int n_in,
                              void* d_out, int out_size)
{
    const float* node_feat = (const float*)d_in[0];
    const float* edge_feat = (const float*)d_in[1];
    const int*   edge_index= (const int*)  d_in[2];
    const float* enW1=(const float*)d_in[3],  *enb1=(const float*)d_in[4];
    const float* enW2=(const float*)d_in[5],  *enb2=(const float*)d_in[6];
    const float* enW3=(const float*)d_in[7],  *enb3=(const float*)d_in[8];
    const float* enlg=(const float*)d_in[9],  *enlb=(const float*)d_in[10];
    const float* eeW1=(const float*)d_in[11], *eeb1=(const float*)d_in[12];
    const float* eeW2=(const float*)d_in[13], *eeb2=(const float*)d_in[14];
    const float* eeW3=(const float*)d_in[15], *eeb3=(const float*)d_in[16];
    const float* eelg=(const float*)d_in[17], *eelb=(const float*)d_in[18];
    const float* procW=(const float*)d_in[19], *procb=(const float*)d_in[20];
    const float* bng =(const float*)d_in[21], *bnb =(const float*)d_in[22];
    const float* dW1=(const float*)d_in[23], *db1=(const float*)d_in[24];
    const float* dW2=(const float*)d_in[25], *db2=(const float*)d_in[26];
    const float* dW3=(const float*)d_in[27], *db3=(const float*)d_in[28];
    const float* dlg=(const float*)d_in[29], *dlb=(const float*)d_in[30];
    float* out = (float*)d_out;

    const int* src = edge_index;
    const int* dst = edge_index + NE;

    float *p_hn,*p_h,*p_x,*p_eacc,*p_dis,*p_selfw,*p_ccoef,*p_bnsum,*p_bnsq;
    int *p_cnt,*p_deg,*p_off,*p_cur,*p_csrc;
    cudaGetSymbolAddress((void**)&p_hn,   g_hn);
    cudaGetSymbolAddress((void**)&p_h,    g_h);
    cudaGetSymbolAddress((void**)&p_x,    g_x);
    cudaGetSymbolAddress((void**)&p_eacc, g_eacc);
    cudaGetSymbolAddress((void**)&p_cnt,  g_cnt);
    cudaGetSymbolAddress((void**)&p_deg,  g_deg);
    cudaGetSymbolAddress((void**)&p_dis,  g_dis);
    cudaGetSymbolAddress((void**)&p_selfw,g_selfw);
    cudaGetSymbolAddress((void**)&p_off,  g_off);
    cudaGetSymbolAddress((void**)&p_cur,  g_cur);
    cudaGetSymbolAddress((void**)&p_csrc, g_csrc);
    cudaGetSymbolAddress((void**)&p_ccoef,g_ccoef);
    cudaGetSymbolAddress((void**)&p_bnsum,g_bnsum);
    cudaGetSymbolAddress((void**)&p_bnsq, g_bnsq);

    // MLP smem: 3*16384 + 2560 + 5*128 + 128 = 52480 floats = 209920 B (1 CTA, 16 warps, 0 barriers)
    const size_t MLP_SMEM  = (size_t)(3*16384 + 2560 + 5*128 + 128) * 4;
    // GEMM smem: 16384 + 256 = 16640 floats = 66560 B (2 CTAs/SM)
    const size_t GEMM_SMEM = (size_t)(16384 + 128 + 128) * 4;
    cudaFuncSetAttribute(mlp3_kernel<19,0>, cudaFuncAttributeMaxDynamicSharedMemorySize, (int)MLP_SMEM);
    cudaFuncSetAttribute(mlp3_kernel<4,1>,  cudaFuncAttributeMaxDynamicSharedMemorySize, (int)MLP_SMEM);
    cudaFuncSetAttribute(mlp3_kernel<128,2>,cudaFuncAttributeMaxDynamicSharedMemorySize, (int)MLP_SMEM);
    cudaFuncSetAttribute(gemm_kernel,       cudaFuncAttributeMaxDynamicSharedMemorySize, (int)GEMM_SMEM);

    const int NODE_TB  = (NN + 127) / 128;     // 391  (MLP tiles)
    const int EDGE_TB  = NE / 128;             // 6250
    const int CONV_TB  = (NN + 63) / 64;       // 782  (conv GEMM tiles)
    const int E_B256   = (NE + 255) / 256;
    const int N_B256   = (NN + 255) / 256;
    const int NV4_B    = (NN*32 + 255) / 256;
    const int AGG_B    = 1184;                 // 148 SMs * 8

    cudaMemsetAsync(p_eacc, 0, (size_t)NN*DD*sizeof(float));
    cudaMemsetAsync(p_cnt,  0, (size_t)NN*sizeof(int));
    cudaMemsetAsync(p_deg,  0, (size_t)NN*sizeof(int));
    deg_kernel<<<E_B256,256>>>(src, dst, p_deg, p_cnt);
    nodeprep_kernel<<<N_B256,256>>>(p_deg, p_dis, p_selfw);
    // node encoder (launch 6)
    mlp3_kernel<19,0><<<NODE_TB,512,MLP_SMEM>>>(node_feat, enW1,enb1,enW2,enb2,enW3,enb3,
                                                enlg,enlb, nullptr, p_hn, NN);
    // edge encoder  <-- ncu capture slot 7
    mlp3_kernel<4,1><<<EDGE_TB,512,MLP_SMEM>>>(edge_feat, eeW1,eeb1,eeW2,eeb2,eeW3,eeb3,
                                               eelg,eelb, src, p_eacc, NE);
    encfin_kernel<<<NV4_B,256>>>(p_hn, p_eacc, p_cnt);
    cudaMemsetAsync(p_cur, 0, (size_t)NN*sizeof(int));
    scan_kernel<<<1,1024>>>(p_deg, p_off);
    fill_kernel<<<E_B256,256>>>(src, dst, p_dis, p_off, p_cur, p_csrc, p_ccoef);

    for (int s = 0; s < NSTEPS; s++){
        const float* W0 = procW + (size_t)(s*2+0)*DD*DD;
        const float* W1 = procW + (size_t)(s*2+1)*DD*DD;
        const float* b0 = procb + (size_t)(s*2+0)*DD;
        const float* b1 = procb + (size_t)(s*2+1)*DD;

        gemm_kernel<<<CONV_TB,256,GEMM_SMEM>>>(p_hn, W0, p_h, NN,
                                               nullptr,nullptr,nullptr,nullptr, 0,
                                               p_bnsum, p_bnsq);
        agg_kernel<1><<<AGG_B,256>>>(p_h, p_off, p_csrc, p_ccoef, p_selfw, b0,
                                     p_x, nullptr, p_bnsum, p_bnsq);

        gemm_kernel<<<CONV_TB,256,GEMM_SMEM>>>(p_x, W1, p_h, NN,
                                               p_bnsum, p_bnsq,
                                               bng + (size_t)s*DD, bnb + (size_t)s*DD, 1,
                                               nullptr, nullptr);
        agg_kernel<2><<<AGG_B,256>>>(p_h, p_off, p_csrc, p_ccoef, p_selfw, b1,
                                     nullptr, p_hn, nullptr, nullptr);
    }

    mlp3_kernel<128,2><<<NODE_TB,512,MLP_SMEM>>>(p_hn, dW1,db1,dW2,db2,dW3,db3,
                                                 dlg,dlb, nullptr, out, NN);
    (void)in_sizes; (void)n_in; (void)out_size;
}

// round 12
// speedup vs baseline: 1.2248x; 1.2248x over previous
#include <cuda_runtime.h>
#include <cstddef>

#define NN 50000
#define NE 800000
#define DD 128
#define NSTEPS 5
#define EPSF 1e-5f

typedef unsigned long long ull;

// ---------------- scratch (static __device__ — no allocation) ----------------
static __device__ float g_hn  [NN*DD];
static __device__ float g_h   [NN*DD];
static __device__ float g_x   [NN*DD];
static __device__ float g_eacc[NN*DD];
static __device__ int   g_cnt [NN];
static __device__ int   g_deg [NN];
static __device__ float g_dis [NN];
static __device__ float g_selfw[NN];
static __device__ int   g_off [NN+1];
static __device__ int   g_cur [NN];
static __device__ int   g_csrc[NE];
static __device__ float g_ccoef[NE];
static __device__ float g_bnsum[DD];
static __device__ float g_bnsq [DD];

// ---------------- helpers ----------------
__device__ __forceinline__ void red_add_v4(float* p, float a, float b, float c, float d){
    asm volatile("red.global.add.v4.f32 [%0], {%1,%2,%3,%4};"
                 :: "l"(p), "f"(a), "f"(b), "f"(c), "f"(d) : "memory");
}
__device__ __forceinline__ ull fma2(ull a, ull b, ull c){
    ull d;
    asm("fma.rn.f32x2 %0, %1, %2, %3;" : "=l"(d) : "l"(a), "l"(b), "l"(c));
    return d;
}
__device__ __forceinline__ float pairsum(ull p){
    unsigned lo, hi;
    asm("mov.b64 {%0,%1}, %2;" : "=r"(lo), "=r"(hi) : "l"(p));
    return __uint_as_float(lo) + __uint_as_float(hi);
}

// Vectorized weight staging: [KD][128] row-major -> k-pair interleaved smem.
// sW2[(kp*128 + c)*2 + {0,1}] = W[2kp][c], W[2kp+1][c]  (odd KD: pad 0).
// Unit u = (kp, c4): 2x LDG.128 in, 2x STS.128 out (layout identical to scalar version).
template<int KD>
__device__ __forceinline__ void load_w2(const float* __restrict__ W, float* __restrict__ sW2, int t){
    constexpr int KP = (KD + 1) / 2;
    for (int u = t; u < KP*32; u += 256){
        int kp = u >> 5, c4 = (u & 31) * 4;
        float4 w0 = *reinterpret_cast<const float4*>(W + (size_t)(2*kp)*128 + c4);
        float4 w1 = (2*kp+1 < KD) ? *reinterpret_cast<const float4*>(W + (size_t)(2*kp+1)*128 + c4)
                                  : make_float4(0.f,0.f,0.f,0.f);
        float* dst = sW2 + (size_t)(kp*128 + c4)*2;
        *reinterpret_cast<float4*>(dst + 0) = make_float4(w0.x, w1.x, w0.y, w1.y);
        *reinterpret_cast<float4*>(dst + 4) = make_float4(w0.z, w1.z, w0.w, w1.w);
    }
}

// r7 proven core: packed-f32x2, 1 k-pair per iteration, unroll 2.
// warp owns 8 rows; lane owns cols lane*4..+3.
template<int KPAIRS>
__device__ __forceinline__ void gemm_core2(const float* __restrict__ xrow, int stride,
                                           const float* __restrict__ sW2, int lane,
                                           ull acc2[8][4])
{
#pragma unroll
    for (int r=0;r<8;r++){ acc2[r][0]=0ull; acc2[r][1]=0ull; acc2[r][2]=0ull; acc2[r][3]=0ull; }
#pragma unroll 2
    for (int kp=0; kp<KPAIRS; kp++){
        const ulonglong2* wp = reinterpret_cast<const ulonglong2*>(sW2 + kp*256);
        ulonglong2 wA = wp[lane*2+0];     // cols lane*4+0, lane*4+1
        ulonglong2 wB = wp[lane*2+1];     // cols lane*4+2, lane*4+3
        ull a[8];
#pragma unroll
        for (int r=0;r<8;r++)
            a[r] = *reinterpret_cast<const ull*>(xrow + r*stride + kp*2);
#pragma unroll
        for (int r=0;r<8;r++){
            acc2[r][0] = fma2(a[r], wA.x, acc2[r][0]);
            acc2[r][1] = fma2(a[r], wA.y, acc2[r][1]);
            acc2[r][2] = fma2(a[r], wB.x, acc2[r][2]);
            acc2[r][3] = fma2(a[r], wB.y, acc2[r][3]);
        }
    }
}

// ---------------- fused 3-layer MLP (+LayerNorm), in-place activation buffer ----------------
// MODE 0: node encoder -> store rows; MODE 1: edge encoder -> LN + red-scatter to out[src];
// MODE 2: decoder -> [nrows,128] input, store rows.
template<int INDIM, int MODE>
__global__ void __launch_bounds__(256,2)
mlp3_kernel(const float* __restrict__ in,
            const float* __restrict__ W1, const float* __restrict__ b1,
            const float* __restrict__ W2, const float* __restrict__ b2,
            const float* __restrict__ W3, const float* __restrict__ b3,
            const float* __restrict__ lng, const float* __restrict__ lnb,
            const int* __restrict__ srcIdx,
            float* __restrict__ out, int nrows)
{
    extern __shared__ float sm[];
    float* sW2  = sm;               // 16384
    float* buf  = sm + 16384;       // 64*132 = 8448
    float* sIn  = buf + 8448;       // 64*20 = 1280
    float* sG   = sIn + 1280;       // 128
    float* sBt  = sG + 128;         // 128
    float* sBias= sBt + 128;        // 128
    int*   sSrc = (int*)(sBias + 128); // 64 ints

    const int t    = threadIdx.x;
    const int lane = t & 31;
    const int warp = t >> 5;
    const int row0 = blockIdx.x * 64;
    constexpr int INPAD = (INDIM==19) ? 20 : (INDIM==4 ? 4 : 132);

    if (t < 128){ sG[t]=lng[t]; sBt[t]=lnb[t]; sBias[t]=b1[t]; }

    if constexpr (MODE == 2){
        for (int i=t;i<64*32;i+=256){
            int r=i>>5, c4=i&31;
            float4 v = (row0+r<nrows) ? reinterpret_cast<const float4*>(in + (size_t)(row0+r)*128)[c4]
                                      : make_float4(0.f,0.f,0.f,0.f);
            reinterpret_cast<float4*>(buf + r*132)[c4] = v;
        }
    } else {
        for (int i=t;i<64*INPAD;i+=256){
            int r=i/INPAD, k=i-r*INPAD;
            sIn[i] = (k < INDIM && row0+r < nrows) ? in[(size_t)(row0+r)*INDIM+k] : 0.f;
        }
    }
    if constexpr (MODE == 1){ if (t<64) sSrc[t]=srcIdx[row0+t]; }
    load_w2<INDIM>(W1, sW2, t);
    __syncthreads();

    ull acc2[8][4];
    float acc[8][4];
    const float* myrows = (MODE==2) ? (buf + warp*8*132) : (sIn + warp*8*INPAD);
    const int mystride  = (MODE==2) ? 132 : INPAD;

    // ---- layer 1 (+leaky) -> buf (in-place safe: warp-private rows) ----
    gemm_core2<(INDIM+1)/2>(myrows, mystride, sW2, lane, acc2);
    {
        float4 b4 = reinterpret_cast<const float4*>(sBias)[lane];
#pragma unroll
        for (int r=0;r<8;r++){
            float4 v;
            v.x = pairsum(acc2[r][0])+b4.x; v.x=(v.x>0.f)?v.x:0.05f*v.x;
            v.y = pairsum(acc2[r][1])+b4.y; v.y=(v.y>0.f)?v.y:0.05f*v.y;
            v.z = pairsum(acc2[r][2])+b4.z; v.z=(v.z>0.f)?v.z:0.05f*v.z;
            v.w = pairsum(acc2[r][3])+b4.w; v.w=(v.w>0.f)?v.w:0.05f*v.w;
            reinterpret_cast<float4*>(buf + (warp*8+r)*132)[lane] = v;
        }
    }
    __syncthreads();
    load_w2<128>(W2, sW2, t);
    if (t<128) sBias[t]=b2[t];
    __syncthreads();

    // ---- layer 2 (+leaky), in-place ----
    gemm_core2<64>(buf + warp*8*132, 132, sW2, lane, acc2);
    {
        float4 b4 = reinterpret_cast<const float4*>(sBias)[lane];
#pragma unroll
        for (int r=0;r<8;r++){
            float4 v;
            v.x = pairsum(acc2[r][0])+b4.x; v.x=(v.x>0.f)?v.x:0.05f*v.x;
            v.y = pairsum(acc2[r][1])+b4.y; v.y=(v.y>0.f)?v.y:0.05f*v.y;
            v.z = pairsum(acc2[r][2])+b4.z; v.z=(v.z>0.f)?v.z:0.05f*v.z;
            v.w = pairsum(acc2[r][3])+b4.w; v.w=(v.w>0.f)?v.w:0.05f*v.w;
            reinterpret_cast<float4*>(buf + (warp*8+r)*132)[lane] = v;
        }
    }
    __syncthreads();
    load_w2<128>(W3, sW2, t);
    if (t<128) sBias[t]=b3[t];
    __syncthreads();

    // ---- layer 3 (linear) + LayerNorm ----
    gemm_core2<64>(buf + warp*8*132, 132, sW2, lane, acc2);
    {
        float4 b4 = reinterpret_cast<const float4*>(sBias)[lane];
        float4 gv = reinterpret_cast<const float4*>(sG)[lane];
        float4 bv = reinterpret_cast<const float4*>(sBt)[lane];
#pragma unroll
        for (int r=0;r<8;r++){
            acc[r][0]=pairsum(acc2[r][0])+b4.x; acc[r][1]=pairsum(acc2[r][1])+b4.y;
            acc[r][2]=pairsum(acc2[r][2])+b4.z; acc[r][3]=pairsum(acc2[r][3])+b4.w;
            float s = acc[r][0]+acc[r][1]+acc[r][2]+acc[r][3];
            float q = acc[r][0]*acc[r][0]+acc[r][1]*acc[r][1]+acc[r][2]*acc[r][2]+acc[r][3]*acc[r][3];
#pragma unroll
            for (int o=16;o>0;o>>=1){
                s += __shfl_xor_sync(0xffffffffu, s, o);
                q += __shfl_xor_sync(0xffffffffu, q, o);
            }
            float m   = s * (1.f/128.f);
            float var = q * (1.f/128.f) - m*m;
            float rs  = rsqrtf(var + EPSF);
            float4 o4;
            o4.x = (acc[r][0]-m)*rs*gv.x + bv.x;
            o4.y = (acc[r][1]-m)*rs*gv.y + bv.y;
            o4.z = (acc[r][2]-m)*rs*gv.z + bv.z;
            o4.w = (acc[r][3]-m)*rs*gv.w + bv.w;
            int row = warp*8 + r;
            if constexpr (MODE == 1){
                int sidx = sSrc[row];
                red_add_v4(out + (size_t)sidx*128 + lane*4, o4.x, o4.y, o4.z, o4.w);
            } else {
                if (row0 + row < nrows)
                    reinterpret_cast<float4*>(out + (size_t)(row0+row)*128)[lane] = o4;
            }
        }
    }
}

// ---------------- conv GEMM [nrows,128]@[128,128], fused BN on input, vector staging ----------------
__global__ void __launch_bounds__(256,2)
gemm_kernel(const float* __restrict__ in, const float* __restrict__ W,
            float* __restrict__ out, int nrows,
            const float* __restrict__ bnsum, const float* __restrict__ bnsq,
            const float* __restrict__ bng, const float* __restrict__ bnb, int useBN,
            float* __restrict__ zsum, float* __restrict__ zsq)
{
    extern __shared__ float sm[];
    float* sW2    = sm;             // 16384
    float* buf    = sm + 16384;     // 8448
    float* sScale = buf + 8448;     // 128
    float* sShift = sScale + 128;   // 128

    const int t    = threadIdx.x;
    const int lane = t & 31;
    const int warp = t >> 5;
    const int row0 = blockIdx.x * 64;

    // zero BN accumulators for the upcoming agg pass (conv1 only, one block)
    if (zsum && blockIdx.x == 0 && t < 128){ zsum[t] = 0.f; zsq[t] = 0.f; }

    if (t < 128){
        if (useBN){
            float mm = bnsum[t]*(1.f/NN);
            float vv = bnsq[t]*(1.f/NN) - mm*mm;
            float rr = rsqrtf(vv + EPSF);
            sScale[t] = rr*bng[t];
            sShift[t] = bnb[t] - mm*rr*bng[t];
        } else { sScale[t]=1.f; sShift[t]=0.f; }
    }
    __syncthreads();

    for (int i=t;i<64*32;i+=256){
        int r=i>>5, c4=i&31;
        float4 v = (row0+r<nrows) ? reinterpret_cast<const float4*>(in + (size_t)(row0+r)*128)[c4]
                                  : make_float4(0.f,0.f,0.f,0.f);
        float4 sc = reinterpret_cast<const float4*>(sScale)[c4];
        float4 sh = reinterpret_cast<const float4*>(sShift)[c4];
        v.x = v.x*sc.x + sh.x; v.y = v.y*sc.y + sh.y;
        v.z = v.z*sc.z + sh.z; v.w = v.w*sc.w + sh.w;
        reinterpret_cast<float4*>(buf + r*132)[c4] = v;
    }
    load_w2<128>(W, sW2, t);
    __syncthreads();

    ull acc2[8][4];
    gemm_core2<64>(buf + warp*8*132, 132, sW2, lane, acc2);
#pragma unroll
    for (int r=0;r<8;r++){
        int row = warp*8 + r;
        if (row0 + row < nrows)
            reinterpret_cast<float4*>(out + (size_t)(row0+row)*128)[lane] =
                make_float4(pairsum(acc2[r][0]),pairsum(acc2[r][1]),
                            pairsum(acc2[r][2]),pairsum(acc2[r][3]));
    }
}

// ---------------- fused CSR aggregation + epilogue (warp per node) ----------------
template<int MODE>
__global__ void __launch_bounds__(256)
agg_kernel(const float* __restrict__ h, const int* __restrict__ off,
           const int* __restrict__ csrc, const float* __restrict__ ccoef,
           const float* __restrict__ selfw, const float* __restrict__ bias,
           float* __restrict__ xout, float* __restrict__ hn,
           float* __restrict__ bnsum, float* __restrict__ bnsq)
{
    __shared__ float sbs[DD], sbq[DD];
    const int t = threadIdx.x, lane = t & 31, w = t >> 5;
    if constexpr (MODE == 1){
        if (t < 128){ sbs[t]=0.f; sbq[t]=0.f; }
        __syncthreads();
    }
    float4 b4 = reinterpret_cast<const float4*>(bias)[lane];
    float s0=0.f,s1=0.f,s2=0.f,s3=0.f,q0=0.f,q1=0.f,q2=0.f,q3=0.f;
    const int nwarps = gridDim.x * 8;

    for (int n = blockIdx.x*8 + w; n < NN; n += nwarps){
        int e0 = off[n], e1 = off[n+1];
        float ax=0.f, ay=0.f, az=0.f, aw=0.f;
        int i = e0;
        for (; i+1 < e1; i += 2){
            int   sA = csrc[i];   float cA = ccoef[i];
            int   sB = csrc[i+1]; float cB = ccoef[i+1];
            float4 vA = reinterpret_cast<const float4*>(h + (size_t)sA*DD)[lane];
            float4 vB = reinterpret_cast<const float4*>(h + (size_t)sB*DD)[lane];
            ax += vA.x*cA + vB.x*cB; ay += vA.y*cA + vB.y*cB;
            az += vA.z*cA + vB.z*cB; aw += vA.w*cA + vB.w*cB;
        }
        if (i < e1){
            int sA = csrc[i]; float cA = ccoef[i];
            float4 vA = reinterpret_cast<const float4*>(h + (size_t)sA*DD)[lane];
            ax += vA.x*cA; ay += vA.y*cA; az += vA.z*cA; aw += vA.w*cA;
        }
        float4 hv = reinterpret_cast<const float4*>(h + (size_t)n*DD)[lane];
        float sw = selfw[n];
        ax += hv.x*sw + b4.x; ay += hv.y*sw + b4.y;
        az += hv.z*sw + b4.z; aw += hv.w*sw + b4.w;
        if constexpr (MODE == 1){
            ax = (ax>0.f)?ax:0.05f*ax; ay = (ay>0.f)?ay:0.05f*ay;
            az = (az>0.f)?az:0.05f*az; aw = (aw>0.f)?aw:0.05f*aw;
            reinterpret_cast<float4*>(xout + (size_t)n*DD)[lane] = make_float4(ax,ay,az,aw);
            s0+=ax;s1+=ay;s2+=az;s3+=aw;
            q0+=ax*ax;q1+=ay*ay;q2+=az*az;q3+=aw*aw;
        } else {
            float4 o = reinterpret_cast<float4*>(hn + (size_t)n*DD)[lane];
            o.x+=ax; o.y+=ay; o.z+=az; o.w+=aw;
            reinterpret_cast<float4*>(hn + (size_t)n*DD)[lane] = o;
        }
    }
    if constexpr (MODE == 1){
        atomicAdd(&sbs[lane*4+0],s0); atomicAdd(&sbs[lane*4+1],s1);
        atomicAdd(&sbs[lane*4+2],s2); atomicAdd(&sbs[lane*4+3],s3);
        atomicAdd(&sbq[lane*4+0],q0); atomicAdd(&sbq[lane*4+1],q1);
        atomicAdd(&sbq[lane*4+2],q2); atomicAdd(&sbq[lane*4+3],q3);
        __syncthreads();
        if (t < 128){ atomicAdd(&bnsum[t], sbs[t]); atomicAdd(&bnsq[t], sbq[t]); }
    }
}

// ---------------- prep kernels ----------------
__global__ void deg_kernel(const int* __restrict__ src, const int* __restrict__ dst,
                           int* __restrict__ degD, int* __restrict__ cntS){
    int e = blockIdx.x*256 + threadIdx.x;
    if (e < NE){ atomicAdd(&degD[dst[e]], 1); atomicAdd(&cntS[src[e]], 1); }
}
__global__ void nodeprep_kernel(const int* __restrict__ degD,
                                float* __restrict__ dis, float* __restrict__ selfw){
    int n = blockIdx.x*256 + threadIdx.x;
    if (n < NN){
        float d = (float)degD[n] + 1.0f;
        dis[n] = rsqrtf(d);
        selfw[n] = 1.0f/d;
    }
}
__global__ void scan_kernel(const int* __restrict__ degD, int* __restrict__ off){
    __shared__ int sh[32];
    __shared__ int carry;
    const int t = threadIdx.x, lane = t & 31, w = t >> 5;
    if (t == 0){ carry = 0; off[0] = 0; }
    __syncthreads();
    for (int base = 0; base < NN; base += 1024){
        int i = base + t;
        int v = (i < NN) ? degD[i] : 0;
        int x = v;
#pragma unroll
        for (int o=1;o<32;o<<=1){ int y=__shfl_up_sync(0xffffffffu,x,o); if (lane>=o) x+=y; }
        if (lane == 31) sh[w] = x;
        __syncthreads();
        if (w == 0){
            int y = sh[lane];
#pragma unroll
            for (int o=1;o<32;o<<=1){ int z=__shfl_up_sync(0xffffffffu,y,o); if (lane>=o) y+=z; }
            sh[lane] = y;
        }
        __syncthreads();
        int add = (w > 0) ? sh[w-1] : 0;
        int incl = x + add + carry;
        if (i < NN) off[i+1] = incl;
        __syncthreads();
        if (t == 1023) carry = incl;
        __syncthreads();
    }
}
__global__ void fill_kernel(const int* __restrict__ src, const int* __restrict__ dst,
                            const float* __restrict__ dis, const int* __restrict__ off,
                            int* __restrict__ cur, int* __restrict__ csrc, float* __restrict__ ccoef){
    int e = blockIdx.x*256 + threadIdx.x;
    if (e < NE){
        int d = dst[e], s = src[e];
        int pos = off[d] + atomicAdd(&cur[d], 1);
        csrc[pos]  = s;
        ccoef[pos] = dis[s]*dis[d];
    }
}
__global__ void encfin_kernel(float* __restrict__ hn, const float* __restrict__ eacc,
                              const int* __restrict__ cnt){
    int i4 = blockIdx.x*256 + threadIdx.x;
    if (i4 >= NN*32) return;
    int n = i4 >> 5;
    float inv = 1.0f / fmaxf((float)cnt[n], 1.0f);
    float4 a  = reinterpret_cast<const float4*>(eacc)[i4];
    float4 hh = reinterpret_cast<float4*>(hn)[i4];
    hh.x += a.x*inv; hh.y += a.y*inv; hh.z += a.z*inv; hh.w += a.w*inv;
    reinterpret_cast<float4*>(hn)[i4] = hh;
}

// ---------------- launcher ----------------
extern "C" void kernel_launch(void* const* d_in, const int* in_sizes, int n_in,
                              void* d_out, int out_size)
{
    const float* node_feat = (const float*)d_in[0];
    const float* edge_feat = (const float*)d_in[1];
    const int*   edge_index= (const int*)  d_in[2];
    const float* enW1=(const float*)d_in[3],  *enb1=(const float*)d_in[4];
    const float* enW2=(const float*)d_in[5],  *enb2=(const float*)d_in[6];
    const float* enW3=(const float*)d_in[7],  *enb3=(const float*)d_in[8];
    const float* enlg=(const float*)d_in[9],  *enlb=(const float*)d_in[10];
    const float* eeW1=(const float*)d_in[11], *eeb1=(const float*)d_in[12];
    const float* eeW2=(const float*)d_in[13], *eeb2=(const float*)d_in[14];
    const float* eeW3=(const float*)d_in[15], *eeb3=(const float*)d_in[16];
    const float* eelg=(const float*)d_in[17], *eelb=(const float*)d_in[18];
    const float* procW=(const float*)d_in[19], *procb=(const float*)d_in[20];
    const float* bng =(const float*)d_in[21], *bnb =(const float*)d_in[22];
    const float* dW1=(const float*)d_in[23], *db1=(const float*)d_in[24];
    const float* dW2=(const float*)d_in[25], *db2=(const float*)d_in[26];
    const float* dW3=(const float*)d_in[27], *db3=(const float*)d_in[28];
    const float* dlg=(const float*)d_in[29], *dlb=(const float*)d_in[30];
    float* out = (float*)d_out;

    const int* src = edge_index;
    const int* dst = edge_index + NE;

    float *p_hn,*p_h,*p_x,*p_eacc,*p_dis,*p_selfw,*p_ccoef,*p_bnsum,*p_bnsq;
    int *p_cnt,*p_deg,*p_off,*p_cur,*p_csrc;
    cudaGetSymbolAddress((void**)&p_hn,   g_hn);
    cudaGetSymbolAddress((void**)&p_h,    g_h);
    cudaGetSymbolAddress((void**)&p_x,    g_x);
    cudaGetSymbolAddress((void**)&p_eacc, g_eacc);
    cudaGetSymbolAddress((void**)&p_cnt,  g_cnt);
    cudaGetSymbolAddress((void**)&p_deg,  g_deg);
    cudaGetSymbolAddress((void**)&p_dis,  g_dis);
    cudaGetSymbolAddress((void**)&p_selfw,g_selfw);
    cudaGetSymbolAddress((void**)&p_off,  g_off);
    cudaGetSymbolAddress((void**)&p_cur,  g_cur);
    cudaGetSymbolAddress((void**)&p_csrc, g_csrc);
    cudaGetSymbolAddress((void**)&p_ccoef,g_ccoef);
    cudaGetSymbolAddress((void**)&p_bnsum,g_bnsum);
    cudaGetSymbolAddress((void**)&p_bnsq, g_bnsq);

    // MLP smem: 16384 + 8448 + 1280 + 3*128 + 64 = 26560 floats = 106240 B (2 CTAs/SM)
    const size_t MLP_SMEM  = (size_t)(16384 + 8448 + 1280 + 128 + 128 + 128 + 64) * 4;
    const size_t GEMM_SMEM = (size_t)(16384 + 8448 + 128 + 128) * 4;
    cudaFuncSetAttribute(mlp3_kernel<19,0>, cudaFuncAttributeMaxDynamicSharedMemorySize, (int)MLP_SMEM);
    cudaFuncSetAttribute(mlp3_kernel<4,1>,  cudaFuncAttributeMaxDynamicSharedMemorySize, (int)MLP_SMEM);
    cudaFuncSetAttribute(mlp3_kernel<128,2>,cudaFuncAttributeMaxDynamicSharedMemorySize, (int)MLP_SMEM);
    cudaFuncSetAttribute(gemm_kernel,       cudaFuncAttributeMaxDynamicSharedMemorySize, (int)GEMM_SMEM);

    const int NODE_TB = (NN + 63) / 64;        // 782
    const int EDGE_TB = NE / 64;               // 12500
    const int E_B256  = (NE + 255) / 256;
    const int N_B256  = (NN + 255) / 256;
    const int NV4_B   = (NN*32 + 255) / 256;
    const int AGG_B   = 1184;                  // 148 SMs * 8

    cudaMemsetAsync(p_eacc, 0, (size_t)NN*DD*sizeof(float));
    cudaMemsetAsync(p_cnt,  0, (size_t)NN*sizeof(int));
    cudaMemsetAsync(p_deg,  0, (size_t)NN*sizeof(int));
    deg_kernel<<<E_B256,256>>>(src, dst, p_deg, p_cnt);
    nodeprep_kernel<<<N_B256,256>>>(p_deg, p_dis, p_selfw);
    // node encoder (launch 6)
    mlp3_kernel<19,0><<<NODE_TB,256,MLP_SMEM>>>(node_feat, enW1,enb1,enW2,enb2,enW3,enb3,
                                                enlg,enlb, nullptr, p_hn, NN);
    // edge encoder  <-- ncu capture slot 7
    mlp3_kernel<4,1><<<EDGE_TB,256,MLP_SMEM>>>(edge_feat, eeW1,eeb1,eeW2,eeb2,eeW3,eeb3,
                                               eelg,eelb, src, p_eacc, NE);
    encfin_kernel<<<NV4_B,256>>>(p_hn, p_eacc, p_cnt);
    cudaMemsetAsync(p_cur, 0, (size_t)NN*sizeof(int));
    scan_kernel<<<1,1024>>>(p_deg, p_off);
    fill_kernel<<<E_B256,256>>>(src, dst, p_dis, p_off, p_cur, p_csrc, p_ccoef);

    for (int s = 0; s < NSTEPS; s++){
        const float* W0 = procW + (size_t)(s*2+0)*DD*DD;
        const float* W1 = procW + (size_t)(s*2+1)*DD*DD;
        const float* b0 = procb + (size_t)(s*2+0)*DD;
        const float* b1 = procb + (size_t)(s*2+1)*DD;

        // conv1 GEMM (block 0 also zeroes BN accumulators for the agg pass)
        gemm_kernel<<<NODE_TB,256,GEMM_SMEM>>>(p_hn, W0, p_h, NN,
                                               nullptr,nullptr,nullptr,nullptr, 0,
                                               p_bnsum, p_bnsq);
        agg_kernel<1><<<AGG_B,256>>>(p_h, p_off, p_csrc, p_ccoef, p_selfw, b0,
                                     p_x, nullptr, p_bnsum, p_bnsq);

        gemm_kernel<<<NODE_TB,256,GEMM_SMEM>>>(p_x, W1, p_h, NN,
                                               p_bnsum, p_bnsq,
                                               bng + (size_t)s*DD, bnb + (size_t)s*DD, 1,
                                               nullptr, nullptr);
        agg_kernel<2><<<AGG_B,256>>>(p_h, p_off, p_csrc, p_ccoef, p_selfw, b1,
                                     nullptr, p_hn, nullptr, nullptr);
    }

    mlp3_kernel<128,2><<<NODE_TB,256,MLP_SMEM>>>(p_hn, dW1,db1,dW2,db2,dW3,db3,
                                                 dlg,dlb, nullptr, out, NN);
    (void)in_sizes; (void)n_in; (void)out_size;
}